// round 8
// baseline (speedup 1.0000x reference)
#include <cuda_runtime.h>
#include <math_constants.h>

// Problem constants (fixed by the dataset shapes)
#define B_  2
#define H_  50
#define W_  50
#define C_  256
#define R_  100
#define PH 7
#define PW 7
#define C4 (C_ / 4)   // 64 float4 lanes

__device__ __forceinline__ float4 fmax4(float4 a, float4 b) {
    return make_float4(fmaxf(a.x, b.x), fmaxf(a.y, b.y),
                       fmaxf(a.z, b.z), fmaxf(a.w, b.w));
}

// One block per OUTPUT BIN (b, roi, row_bin, col_bin): 9800 blocks x 64 threads.
// Max occupancy (32-blocks/SM HW limit binds), perfect load balance across
// bins (no intra-block tail wait), dual-accumulator unroll for MLP.
__global__ void __launch_bounds__(C4, 24) roi_pool_kernel(
    const float* __restrict__ fm,     // (B, H, W, C)
    const float* __restrict__ rois,   // (B, R, 4)
    float* __restrict__ out)          // (B, R, PH, PW, C)
{
    const int blk = blockIdx.x;
    const int j  = blk % PW;                     // column bin
    const int bi = (blk / PW) % PH;              // row bin
    const int r  = (blk / (PW * PH)) % R_;
    const int b  = blk / (PW * PH * R_);
    const int c4 = threadIdx.x;                  // float4 channel index

    const float4 roi = *reinterpret_cast<const float4*>(rois + (size_t)(b * R_ + r) * 4);

    // Mirror reference: truncating cast of f32 products (all coords >= 0)
    const int hs = (int)(H_ * roi.x);
    const int ws = (int)(W_ * roi.y);
    const int he = (int)(H_ * roi.z);
    const int we = (int)(W_ * roi.w);

    const int sh = max((he - hs) / PH, 1);
    const int sw = max((we - ws) / PW, 1);

    // Row/col range for this bin. Last bin absorbs the remainder.
    const int y0 = hs + bi * sh;
    const int y1 = (bi == PH - 1) ? he : min(hs + (bi + 1) * sh, he);
    const int x0 = ws + j * sw;
    const int x1 = (j == PW - 1) ? we : min(ws + (j + 1) * sw, we);

    const float4* __restrict__ fmb =
        reinterpret_cast<const float4*>(fm + (size_t)b * H_ * W_ * C_) + c4;

    const float4 NEG_INF4 = make_float4(-CUDART_INF_F, -CUDART_INF_F,
                                        -CUDART_INF_F, -CUDART_INF_F);
    float4 a0 = NEG_INF4;
    float4 a1 = NEG_INF4;

    #pragma unroll 2
    for (int y = y0; y < y1; ++y) {
        const float4* __restrict__ row = fmb + (size_t)y * (W_ * C4);
        int x = x0;
        // 2-way x-unroll: two independent accumulator chains per row
        for (; x + 1 < x1; x += 2) {
            float4 v0 = __ldg(row + (size_t)x * C4);
            float4 v1 = __ldg(row + (size_t)(x + 1) * C4);
            a0 = fmax4(a0, v0);
            a1 = fmax4(a1, v1);
        }
        if (x < x1) {
            a0 = fmax4(a0, __ldg(row + (size_t)x * C4));
        }
    }

    float4* __restrict__ o = reinterpret_cast<float4*>(
        out + ((((size_t)(b * R_ + r)) * PH + bi) * PW + j) * C_) + c4;
    *o = fmax4(a0, a1);
}

extern "C" void kernel_launch(void* const* d_in, const int* in_sizes, int n_in,
                              void* d_out, int out_size)
{
    const float* fm   = (const float*)d_in[0];   // feature_map (2,50,50,256)
    const float* rois = (const float*)d_in[1];   // rois (2,100,4)
    float* out = (float*)d_out;                  // (2,100,7,7,256)

    (void)in_sizes; (void)n_in; (void)out_size;

    dim3 grid(B_ * R_ * PH * PW);
    dim3 block(C4);
    roi_pool_kernel<<<grid, block>>>(fm, rois, out);
}

// round 9
// speedup vs baseline: 1.2045x; 1.2045x over previous
#include <cuda_runtime.h>
#include <math_constants.h>

// Problem constants (fixed by the dataset shapes)
#define B_  2
#define H_  50
#define W_  50
#define C_  256
#define R_  100
#define PH 7
#define PW 7
#define C4 (C_ / 4)   // 64 float4 lanes

__device__ __forceinline__ float4 fmax4(float4 a, float4 b) {
    return make_float4(fmaxf(a.x, b.x), fmaxf(a.y, b.y),
                       fmaxf(a.z, b.z), fmaxf(a.w, b.w));
}

// One block per (b, roi, row_bin). Block = (64 float4-lanes, 7 column-bins):
// each thread computes exactly one output bin. __launch_bounds__(448,4)
// forces regs<=36 so 4 blocks/SM fit -> 87.5% occupancy.
__global__ void __launch_bounds__(C4 * PW, 4) roi_pool_kernel(
    const float* __restrict__ fm,     // (B, H, W, C)
    const float* __restrict__ rois,   // (B, R, 4)
    float* __restrict__ out)          // (B, R, PH, PW, C)
{
    const int blk = blockIdx.x;
    const int bi = blk % PH;                 // row bin
    const int r  = (blk / PH) % R_;
    const int b  = blk / (PH * R_);
    const int c4 = threadIdx.x;              // float4 channel index
    const int j  = threadIdx.y;              // column bin

    const float4 roi = *reinterpret_cast<const float4*>(rois + (size_t)(b * R_ + r) * 4);

    // Mirror reference: truncating cast of f32 products (all coords >= 0)
    const int hs = (int)(H_ * roi.x);
    const int ws = (int)(W_ * roi.y);
    const int he = (int)(H_ * roi.z);
    const int we = (int)(W_ * roi.w);

    const int sh = max((he - hs) / PH, 1);
    const int sw = max((we - ws) / PW, 1);

    // Row range for this row-bin; column range for this col-bin.
    // Last bin absorbs the remainder.
    const int y0 = hs + bi * sh;
    const int y1 = (bi == PH - 1) ? he : min(hs + (bi + 1) * sh, he);
    const int x0 = ws + j * sw;
    const int x1 = (j == PW - 1) ? we : min(ws + (j + 1) * sw, we);

    const float4* __restrict__ fmb =
        reinterpret_cast<const float4*>(fm + (size_t)b * H_ * W_ * C_) + c4;

    const float4 NEG_INF4 = make_float4(-CUDART_INF_F, -CUDART_INF_F,
                                        -CUDART_INF_F, -CUDART_INF_F);
    float4 a0 = NEG_INF4;
    float4 a1 = NEG_INF4;

    for (int y = y0; y < y1; ++y) {
        const float4* __restrict__ row = fmb + (size_t)y * (W_ * C4);
        int x = x0;
        // 2-way x-unroll: two independent accumulator chains per row
        for (; x + 1 < x1; x += 2) {
            float4 v0 = __ldg(row + (size_t)x * C4);
            float4 v1 = __ldg(row + (size_t)(x + 1) * C4);
            a0 = fmax4(a0, v0);
            a1 = fmax4(a1, v1);
        }
        if (x < x1) {
            a0 = fmax4(a0, __ldg(row + (size_t)x * C4));
        }
    }

    float4* __restrict__ o = reinterpret_cast<float4*>(
        out + ((((size_t)(b * R_ + r)) * PH + bi) * PW + j) * C_) + c4;
    *o = fmax4(a0, a1);
}

extern "C" void kernel_launch(void* const* d_in, const int* in_sizes, int n_in,
                              void* d_out, int out_size)
{
    const float* fm   = (const float*)d_in[0];   // feature_map (2,50,50,256)
    const float* rois = (const float*)d_in[1];   // rois (2,100,4)
    float* out = (float*)d_out;                  // (2,100,7,7,256)

    (void)in_sizes; (void)n_in; (void)out_size;

    dim3 grid(B_ * R_ * PH);
    dim3 block(C4, PW);
    roi_pool_kernel<<<grid, block>>>(fm, rois, out);
}